// round 4
// baseline (speedup 1.0000x reference)
#include <cuda_runtime.h>
#include <cuda_bf16.h>

// CRF negative log-likelihood, fixed shapes.
#define B_ 256
#define S_ 1024
#define T_ 64
#define PF 8   // emission prefetch ring depth; renorm every 4 steps

__device__ float g_diff[B_];

// One batch per block, 128 threads: tag = tid>>1, half = tid&1.
// Each thread computes half of the 64-element dot; pair combines via shfl_xor.
// grid=256 -> 2 blocks/SM -> 2 independent warps per SMSP (latency hiding).
__global__ void __launch_bounds__(128) crf_forward_kernel(
    const float* __restrict__ emissions,   // (B, S, T)
    const int* __restrict__ tags,          // (B, S) int32
    const float* __restrict__ trans,       // (T, T)
    const float* __restrict__ startT,      // (T,)
    const float* __restrict__ endT)        // (T,)
{
    const int tid  = threadIdx.x;
    const int tag  = tid >> 1;           // output tag this thread contributes to
    const int half = tid & 1;            // which half of the dot product
    const int b    = blockIdx.x;

    __shared__ __align__(16) float u[2][T_];
    __shared__ float redA[T_];
    __shared__ float redB[128];

    // Per-thread half-column of E = exp(trans): rows [half*32, half*32+32).
    float Ecol[32];
#pragma unroll
    for (int i = 0; i < 32; ++i)
        Ecol[i] = __expf(__ldg(trans + (half * 32 + i) * T_ + tag));

    const float* emb = emissions + (size_t)b * S_ * T_ + tag;

    // t = 0: u0 = exp(start + em0)
    float v = __expf(__ldg(startT + tag) + __ldg(emb));
    if (half == 0) u[0][tag] = v;
    double c = 0.0;   // running log-scale (thread 0 only)

    // Prefetch ring for emissions (em[t][tag] for t = 1..PF)
    float pf[PF];
#pragma unroll
    for (int k = 0; k < PF; ++k)
        pf[k] = __ldg(emb + (size_t)(1 + k) * T_);

    __syncthreads();

    int cur = 0;
    int t = 1;

#pragma unroll 1
    for (int tb = 0; tb < 127; ++tb) {
#pragma unroll
        for (int k = 0; k < 8; ++k, ++t) {
            float em_t = pf[k];
            if (t + PF < S_)
                pf[k] = __ldg(emb + (size_t)(t + PF) * T_);

            const float* ub = u[cur] + half * 32;

            float scale_mul = __expf(em_t);
            if ((k & 3) == 0) {
                float scale = u[cur][0];          // broadcast LDS
                if (tid == 0) c += (double)__logf(scale);
                scale_mul *= __frcp_rn(scale);
            }

            float a0 = 0.f, a1 = 0.f, a2 = 0.f, a3 = 0.f;
            const float4* u4 = reinterpret_cast<const float4*>(ub);
#pragma unroll
            for (int i = 0; i < 8; ++i) {
                float4 uu = u4[i];
                a0 = fmaf(uu.x, Ecol[4 * i + 0], a0);
                a1 = fmaf(uu.y, Ecol[4 * i + 1], a1);
                a2 = fmaf(uu.z, Ecol[4 * i + 2], a2);
                a3 = fmaf(uu.w, Ecol[4 * i + 3], a3);
            }
            float s = (a0 + a1) + (a2 + a3);
            s += __shfl_xor_sync(0xffffffffu, s, 1);   // combine the two halves
            v = s * scale_mul;

            cur ^= 1;
            if (half == 0) u[cur][tag] = v;
            __syncthreads();
        }
    }
    // remainder: t = 1017..1023 (7 steps)
#pragma unroll
    for (int k = 0; k < 7; ++k, ++t) {
        float em_t = pf[k];
        const float* ub = u[cur] + half * 32;

        float scale_mul = __expf(em_t);
        if ((k & 3) == 0) {
            float scale = u[cur][0];
            if (tid == 0) c += (double)__logf(scale);
            scale_mul *= __frcp_rn(scale);
        }

        float a0 = 0.f, a1 = 0.f, a2 = 0.f, a3 = 0.f;
        const float4* u4 = reinterpret_cast<const float4*>(ub);
#pragma unroll
        for (int i = 0; i < 8; ++i) {
            float4 uu = u4[i];
            a0 = fmaf(uu.x, Ecol[4 * i + 0], a0);
            a1 = fmaf(uu.y, Ecol[4 * i + 1], a1);
            a2 = fmaf(uu.z, Ecol[4 * i + 2], a2);
            a3 = fmaf(uu.w, Ecol[4 * i + 3], a3);
        }
        float s = (a0 + a1) + (a2 + a3);
        s += __shfl_xor_sync(0xffffffffu, s, 1);
        v = s * scale_mul;

        cur ^= 1;
        if (half == 0) u[cur][tag] = v;
        __syncthreads();
    }

    // partition = c + log(sum_tag v_tag * exp(end_tag))
    if (half == 0) redA[tag] = v * __expf(__ldg(endT + tag));

    // Gold-path score, parallel over time steps (all 128 threads).
    float sc = 0.f;
    const int* tg = tags + (size_t)b * S_;
    const float* emB = emissions + (size_t)b * S_ * T_;
#pragma unroll 2
    for (int tt = tid; tt < S_; tt += 128) {
        int tg0 = tg[tt];
        sc += __ldg(emB + (size_t)tt * T_ + tg0);
        if (tt + 1 < S_) {
            int tg1 = tg[tt + 1];
            sc += __ldg(trans + tg0 * T_ + tg1);
        }
    }
    if (tid == 0) {
        sc += __ldg(startT + tg[0]);
        sc += __ldg(endT + tg[S_ - 1]);
    }
    redB[tid] = sc;
    __syncthreads();

    if (tid == 0) {
        float sumw = 0.f;
#pragma unroll
        for (int i = 0; i < T_; ++i) sumw += redA[i];
        float sums = 0.f;
#pragma unroll
        for (int i = 0; i < 128; ++i) sums += redB[i];
        double partition = c + (double)__logf(sumw);
        g_diff[b] = (float)(partition - (double)sums);
    }
}

__global__ void crf_reduce_kernel(float* __restrict__ out)
{
    __shared__ float sh[B_];
    int t = threadIdx.x;
    sh[t] = g_diff[t];
    __syncthreads();
#pragma unroll
    for (int off = B_ / 2; off > 0; off >>= 1) {
        if (t < off) sh[t] += sh[t + off];
        __syncthreads();
    }
    if (t == 0) out[0] = sh[0] / (float)B_;
}

extern "C" void kernel_launch(void* const* d_in, const int* in_sizes, int n_in,
                              void* d_out, int out_size)
{
    const float* emissions = (const float*)d_in[0];
    const int*   tags      = (const int*)d_in[1];
    const float* trans     = (const float*)d_in[2];
    const float* startT    = (const float*)d_in[3];
    const float* endT      = (const float*)d_in[4];
    float* out = (float*)d_out;

    crf_forward_kernel<<<B_, 128>>>(emissions, tags, trans, startT, endT);
    crf_reduce_kernel<<<1, B_>>>(out);
}